// round 1
// baseline (speedup 1.0000x reference)
#include <cuda_runtime.h>
#include <math.h>

// ---------------------------------------------------------------------------
// FNO2d: B=8, CIN=2, COUT=1, W0=64, MX=MY=16, NL=4, H=W=256
// Spectral conv uses only modes [:16,:16] (one-sided) -> truncated dense DFT.
// ---------------------------------------------------------------------------

#define Bb 8
#define C0 64
#define Hh 256
#define Ww 256
#define MX 16
#define NLAYERS 4

// -------------------- device global scratch (no cudaMalloc allowed) --------
__device__ float  g_ha[(size_t)Bb * C0 * Hh * Ww];   // 134 MB
__device__ float  g_hb[(size_t)Bb * C0 * Hh * Ww];   // 134 MB
__device__ float2 g_T [(size_t)Bb * C0 * Hh * MX];   // forward, after w-DFT
__device__ float2 g_Xf[(size_t)Bb * C0 * MX * MX];   // forward, after h-DFT
__device__ float2 g_G [(size_t)Bb * C0 * MX * MX];   // after mode GEMM
__device__ float2 g_Q [(size_t)Bb * C0 * Hh * MX];   // inverse, after kx stage
// twiddle tables
__device__ float2 g_Fw[MX * Ww];   // (1/256) e^{-2pi i ky w / 256}
__device__ float2 g_Fh[MX * Hh];   // e^{-2pi i kx h / 256}
__device__ float2 g_Eh[Hh * MX];   // e^{+2pi i kx h / 256}
__device__ float2 g_Ew[MX * Ww];   // c_ky (1/256) e^{+2pi i ky w / 256}

// -------------------- twiddle tables ---------------------------------------
__global__ void k_tables() {
    int idx = blockIdx.x * 256 + threadIdx.x;   // 0..4095
    int a = idx >> 8;       // ky or kx  (0..15)
    int p = idx & 255;      // w  or h   (0..255)
    int m = (a * p) & 255;
    float s, c;
    sincospif((float)m * (1.0f / 128.0f), &s, &c);   // angle = 2*pi*m/256
    const float n = 1.0f / 256.0f;
    g_Fw[idx] = make_float2(c * n, -s * n);
    float ck = (a == 0) ? n : 2.0f * n;
    g_Ew[idx] = make_float2(c * ck, s * ck);
    g_Fh[idx] = make_float2(c, -s);
    g_Eh[p * MX + a] = make_float2(c, s);
}

// -------------------- gelu (exact erf, matches jax approximate=False) ------
__device__ __forceinline__ float gelu_exact(float z) {
    return 0.5f * z * (1.0f + erff(z * 0.70710678118654752f));
}

// -------------------- lift: 2->64 channels + forward w-DFT epilogue --------
__global__ __launch_bounds__(256, 2)
void k_lift(const float* __restrict__ x, const float* __restrict__ in_w,
            const float* __restrict__ in_b) {
    extern __shared__ float sm[];
    float*  nxt_s = sm;                        // [64][257]
    float2* fw_s  = (float2*)(sm + 64 * 257);  // [16][257]
    int h = blockIdx.x, b = blockIdx.y, t = threadIdx.x;

    for (int i = t; i < MX * Ww; i += 256) {
        int ky = i >> 8, w = i & 255;
        fw_s[ky * 257 + w] = g_Fw[i];
    }
    float x0 = x[(((size_t)b * 2 + 0) * Hh + h) * Ww + t];
    float x1 = x[(((size_t)b * 2 + 1) * Hh + h) * Ww + t];
    __syncthreads();

    size_t base = (((size_t)b * C0) * Hh + h) * Ww + t;
    for (int o = 0; o < C0; o++) {
        float v = fmaf(in_w[2 * o], x0, fmaf(in_w[2 * o + 1], x1, in_b[o]));
        nxt_s[o * 257 + t] = v;
        g_ha[base + (size_t)o * (Hh * Ww)] = v;
    }
    __syncthreads();

    // T[b][o][h][ky] = sum_w v(o,w) * Fw[ky][w]
    #pragma unroll
    for (int pass = 0; pass < 4; pass++) {
        int o = (t >> 4) + 16 * pass, ky = t & 15;
        float ar = 0.f, ai = 0.f;
        for (int w = 0; w < Ww; w++) {
            float v = nxt_s[o * 257 + w];
            float2 f = fw_s[ky * 257 + w];
            ar = fmaf(v, f.x, ar);
            ai = fmaf(v, f.y, ai);
        }
        g_T[((((size_t)b * C0 + o) * Hh) + h) * MX + ky] = make_float2(ar, ai);
    }
}

// -------------------- forward h-DFT: T -> Xf --------------------------------
__global__ void k_fwd_h() {
    int bc = blockIdx.x, t = threadIdx.x;
    int kx = t >> 4, ky = t & 15;
    const float2* Trow = g_T + (size_t)bc * Hh * MX;
    const float2* Fh = g_Fh + kx * Hh;
    float ar = 0.f, ai = 0.f;
    for (int h = 0; h < Hh; h++) {
        float2 tv = Trow[h * MX + ky];
        float2 f  = Fh[h];
        ar = fmaf(tv.x, f.x, ar); ar = fmaf(-tv.y, f.y, ar);
        ai = fmaf(tv.x, f.y, ai); ai = fmaf( tv.y, f.x, ai);
    }
    g_Xf[(size_t)bc * 256 + t] = make_float2(ar, ai);
}

// -------------------- per-mode complex channel GEMM: Xf -> G ----------------
__global__ void k_modegemm(const float* __restrict__ wr, const float* __restrict__ wi) {
    __shared__ float  wsr[4096], wsi[4096];
    __shared__ float2 xfs[512];
    int m = blockIdx.x, t = threadIdx.x;   // 512 threads
    for (int i = t; i < 4096; i += 512) {
        wsr[i] = wr[(size_t)i * 256 + m];  // [(i*64+o)][mode]
        wsi[i] = wi[(size_t)i * 256 + m];
    }
    {   // xfs[b*64+i]
        int b = t >> 6, i = t & 63;
        xfs[t] = g_Xf[((size_t)b * C0 + i) * 256 + m];
    }
    __syncthreads();
    int b = t >> 6, o = t & 63;
    float ar = 0.f, ai = 0.f;
    for (int i2 = 0; i2 < C0; i2++) {
        float2 xv = xfs[b * C0 + i2];
        float wrv = wsr[i2 * 64 + o], wiv = wsi[i2 * 64 + o];
        ar = fmaf(xv.x, wrv, ar); ar = fmaf(-xv.y, wiv, ar);
        ai = fmaf(xv.x, wiv, ai); ai = fmaf( xv.y, wrv, ai);
    }
    g_G[((size_t)b * C0 + o) * 256 + m] = make_float2(ar, ai);
}

// -------------------- inverse kx stage: G -> Q ------------------------------
__global__ void k_inv_h() {
    __shared__ float2 Gs[256];
    int bo = blockIdx.x, t = threadIdx.x;
    Gs[t] = g_G[(size_t)bo * 256 + t];
    __syncthreads();
    int hg = t >> 4, ky = t & 15;
    for (int hp = 0; hp < 16; hp++) {
        int h = hp * 16 + hg;
        float ar = 0.f, ai = 0.f;
        #pragma unroll
        for (int kx = 0; kx < MX; kx++) {
            float2 e = g_Eh[h * MX + kx];
            float2 g = Gs[kx * MX + ky];
            ar = fmaf(e.x, g.x, ar); ar = fmaf(-e.y, g.y, ar);
            ai = fmaf(e.x, g.y, ai); ai = fmaf( e.y, g.x, ai);
        }
        g_Q[((size_t)bo * Hh + h) * MX + ky] = make_float2(ar, ai);
    }
}

// -------------------- fused layer: pointwise + inverse-w + gelu + fwd-w ----
template <bool WRITE_T>
__global__ __launch_bounds__(256, 2)
void k_layer(const float* __restrict__ cur, float* __restrict__ nxt,
             const float* __restrict__ pw_w, const float* __restrict__ pw_b) {
    extern __shared__ float sm[];
    float* nxt_s   = sm;                  // [64][257]
    float* regionB = sm + 64 * 257;       // phase1: pw_s[4096] + q_s[1024]f2; phase2: fw_s[16][257]f2
    int h = blockIdx.x, b = blockIdx.y, t = threadIdx.x;

    float*  pw_s = regionB;
    float2* q_s  = (float2*)(regionB + 4096);
    for (int i = t; i < 4096; i += 256) pw_s[i] = pw_w[i];
    for (int i = t; i < 1024; i += 256) {
        int o = i >> 4, ky = i & 15;
        q_s[i] = g_Q[(((size_t)b * C0 + o) * Hh + h) * MX + ky];
    }

    float xr[64];
    size_t base = (((size_t)b * C0) * Hh + h) * Ww + t;
    #pragma unroll
    for (int c = 0; c < C0; c++) xr[c] = cur[base + (size_t)c * (Hh * Ww)];

    float ewr[16], ewi[16];
    #pragma unroll
    for (int ky = 0; ky < MX; ky++) {
        float2 e = g_Ew[ky * Ww + t];
        ewr[ky] = e.x; ewi[ky] = e.y;
    }
    __syncthreads();

    const float4* pw4 = (const float4*)pw_s;
    for (int o = 0; o < C0; o++) {
        float acc = pw_b[o];
        #pragma unroll
        for (int j = 0; j < 16; j++) {
            float4 p = pw4[o * 16 + j];
            acc = fmaf(p.x, xr[4 * j + 0], acc);
            acc = fmaf(p.y, xr[4 * j + 1], acc);
            acc = fmaf(p.z, xr[4 * j + 2], acc);
            acc = fmaf(p.w, xr[4 * j + 3], acc);
        }
        float s1 = 0.f;
        #pragma unroll
        for (int ky = 0; ky < MX; ky++) {
            float2 q = q_s[o * MX + ky];
            s1 = fmaf(q.x, ewr[ky], s1);
            s1 = fmaf(-q.y, ewi[ky], s1);
        }
        float v = gelu_exact(acc + s1);
        nxt_s[o * 257 + t] = v;
        nxt[base + (size_t)o * (Hh * Ww)] = v;
    }

    if (WRITE_T) {
        __syncthreads();                       // phase1 done with regionB
        float2* fw_s = (float2*)regionB;
        for (int i = t; i < MX * Ww; i += 256) {
            int ky = i >> 8, w = i & 255;
            fw_s[ky * 257 + w] = g_Fw[i];
        }
        __syncthreads();
        #pragma unroll
        for (int pass = 0; pass < 4; pass++) {
            int o = (t >> 4) + 16 * pass, ky = t & 15;
            float ar = 0.f, ai = 0.f;
            for (int w = 0; w < Ww; w++) {
                float v = nxt_s[o * 257 + w];
                float2 f = fw_s[ky * 257 + w];
                ar = fmaf(v, f.x, ar);
                ai = fmaf(v, f.y, ai);
            }
            g_T[(((size_t)b * C0 + o) * Hh + h) * MX + ky] = make_float2(ar, ai);
        }
    }
}

// -------------------- head: gelu(64->32) -> 32->1 ---------------------------
__global__ __launch_bounds__(256, 2)
void k_head(const float* __restrict__ cur, float* __restrict__ out,
            const float* __restrict__ o1w, const float* __restrict__ o1b,
            const float* __restrict__ o2w, const float* __restrict__ o2b) {
    __shared__ float w1[2048];
    __shared__ float w2[32];
    int h = blockIdx.x, b = blockIdx.y, t = threadIdx.x;
    for (int i = t; i < 2048; i += 256) w1[i] = o1w[i];
    if (t < 32) w2[t] = o2w[t];

    float xr[64];
    size_t base = (((size_t)b * C0) * Hh + h) * Ww + t;
    #pragma unroll
    for (int c = 0; c < C0; c++) xr[c] = cur[base + (size_t)c * (Hh * Ww)];
    __syncthreads();

    float acc = o2b[0];
    for (int o = 0; o < 32; o++) {
        float s = o1b[o];
        const float4* w4 = (const float4*)(w1 + o * 64);
        #pragma unroll
        for (int j = 0; j < 16; j++) {
            float4 p = w4[j];
            s = fmaf(p.x, xr[4 * j + 0], s);
            s = fmaf(p.y, xr[4 * j + 1], s);
            s = fmaf(p.z, xr[4 * j + 2], s);
            s = fmaf(p.w, xr[4 * j + 3], s);
        }
        acc = fmaf(w2[o], gelu_exact(s), acc);
    }
    out[((size_t)b * Hh + h) * Ww + t] = acc;
}

// ---------------------------------------------------------------------------
extern "C" void kernel_launch(void* const* d_in, const int* in_sizes, int n_in,
                              void* d_out, int out_size) {
    const float* x       = (const float*)d_in[0];
    const float* in_w    = (const float*)d_in[1];
    const float* in_b    = (const float*)d_in[2];
    const float* spec_wr = (const float*)d_in[3];
    const float* spec_wi = (const float*)d_in[4];
    const float* pw_w    = (const float*)d_in[5];
    const float* pw_b    = (const float*)d_in[6];
    const float* o1w     = (const float*)d_in[7];
    const float* o1b     = (const float*)d_in[8];
    const float* o2w     = (const float*)d_in[9];
    const float* o2b     = (const float*)d_in[10];
    float* out = (float*)d_out;

    const size_t smem_fused = (size_t)(64 * 257) * 4 + (size_t)(16 * 257) * 8; // 98688 B
    cudaFuncSetAttribute(k_lift, cudaFuncAttributeMaxDynamicSharedMemorySize, (int)smem_fused);
    cudaFuncSetAttribute(k_layer<true>,  cudaFuncAttributeMaxDynamicSharedMemorySize, (int)smem_fused);
    cudaFuncSetAttribute(k_layer<false>, cudaFuncAttributeMaxDynamicSharedMemorySize, (int)smem_fused);

    float *ha, *hb;
    cudaGetSymbolAddress((void**)&ha, g_ha);
    cudaGetSymbolAddress((void**)&hb, g_hb);

    k_tables<<<16, 256>>>();

    dim3 grid(Hh, Bb);
    k_lift<<<grid, 256, smem_fused>>>(x, in_w, in_b);

    const float* cur = ha;
    float* nxt = hb;
    for (int l = 0; l < NLAYERS; l++) {
        k_fwd_h<<<Bb * C0, 256>>>();
        k_modegemm<<<256, 512>>>(spec_wr + (size_t)l * C0 * C0 * 256,
                                 spec_wi + (size_t)l * C0 * C0 * 256);
        k_inv_h<<<Bb * C0, 256>>>();
        if (l < NLAYERS - 1)
            k_layer<true><<<grid, 256, smem_fused>>>(cur, nxt, pw_w + l * 4096, pw_b + l * 64);
        else
            k_layer<false><<<grid, 256, smem_fused>>>(cur, nxt, pw_w + l * 4096, pw_b + l * 64);
        const float* tmp = cur; cur = nxt; nxt = (float*)tmp;
    }

    k_head<<<grid, 256>>>(cur, out, o1w, o1b, o2w, o2b);
}

// round 2
// speedup vs baseline: 1.0761x; 1.0761x over previous
#include <cuda_runtime.h>
#include <math.h>

// ---------------------------------------------------------------------------
// FNO2d: B=8, CIN=2, COUT=1, W0=64, MX=MY=16, NL=4, H=W=256
// Truncated dense DFTs + packed f32x2 FMA everywhere.
// ---------------------------------------------------------------------------

#define Bb 8
#define C0 64
#define Hh 256
#define Ww 256
#define MX 16
#define NLAYERS 4
#define HW (Hh * Ww)

typedef unsigned long long ull;

// -------------------- packed f32x2 helpers ---------------------------------
__device__ __forceinline__ ull pk(float lo, float hi) {
    ull r; asm("mov.b64 %0,{%1,%2};" : "=l"(r) : "f"(lo), "f"(hi)); return r;
}
__device__ __forceinline__ void upk(ull v, float& lo, float& hi) {
    asm("mov.b64 {%0,%1},%2;" : "=f"(lo), "=f"(hi) : "l"(v));
}
__device__ __forceinline__ ull f2fma(ull a, ull b, ull c) {
    ull d; asm("fma.rn.f32x2 %0,%1,%2,%3;" : "=l"(d) : "l"(a), "l"(b), "l"(c)); return d;
}

// -------------------- device global scratch --------------------------------
__device__ float g_ha[(size_t)Bb * C0 * HW];          // 134 MB
__device__ float g_hb[(size_t)Bb * C0 * HW];          // 134 MB
__device__ ull   g_T [(size_t)Bb * C0 * Hh * MX];     // (re,im) packed
__device__ ull   g_Xf[(size_t)Bb * C0 * 256];
__device__ ull   g_G [(size_t)256 * Bb * C0];         // [mode][b*64+o]
__device__ ull   g_Q [(size_t)Bb * C0 * Hh * MX];
__device__ ull   g_W2[(size_t)NLAYERS * 256 * 4096];  // [l][mode][i*64+o]=(wr,wi) 33.5MB
// twiddle tables (packed)
__device__ ull g_FwR[MX * 128];    // (fr_w, fr_{w+1})   fr = cos/256
__device__ ull g_FwI[MX * 128];    // (fi_w, fi_{w+1})   fi = -sin/256
__device__ ull g_Ew2n[MX * Ww];    // (c*cos/256, -c*sin/256)
__device__ ull g_Fh2a[MX * Hh];    // (cos, -sin)
__device__ ull g_Fh2b[MX * Hh];    // (sin,  cos)
__device__ ull g_Eh2a[Hh * MX];    // (cos,  sin)   [h][kx]
__device__ ull g_Eh2b[Hh * MX];    // (-sin, cos)

// -------------------- tables ------------------------------------------------
__global__ void k_tables() {
    int idx = blockIdx.x * 256 + threadIdx.x;   // 0..4095
    int a = idx >> 8;       // ky or kx
    int p = idx & 255;      // w  or h
    int m = (a * p) & 255;
    float s, c;
    sincospif((float)m * (1.0f / 128.0f), &s, &c);
    float ck = ((a == 0) ? 1.0f : 2.0f) * (1.0f / 256.0f);
    g_Ew2n[idx] = pk(c * ck, -s * ck);
    g_Fh2a[idx] = pk(c, -s);
    g_Fh2b[idx] = pk(s, c);
    g_Eh2a[p * MX + a] = pk(c, s);
    g_Eh2b[p * MX + a] = pk(-s, c);
}
__global__ void k_tables2() {
    int idx = blockIdx.x * 256 + threadIdx.x;   // 0..2047
    int ky = idx >> 7, j = idx & 127, w = 2 * j;
    float s0, c0, s1, c1;
    sincospif((float)((ky * w) & 255) * (1.0f / 128.0f), &s0, &c0);
    sincospif((float)((ky * (w + 1)) & 255) * (1.0f / 128.0f), &s1, &c1);
    const float n = 1.0f / 256.0f;
    g_FwR[idx] = pk(c0 * n, c1 * n);
    g_FwI[idx] = pk(-s0 * n, -s1 * n);
}

// -------------------- spectral weight transpose ----------------------------
__global__ void k_twt(const float* __restrict__ wr, const float* __restrict__ wi) {
    __shared__ ull tile[32][33];
    int l = blockIdx.z, tio = blockIdx.x, tm = blockIdx.y;
    int tx = threadIdx.x, ty = threadIdx.y;
    const float* wrl = wr + (size_t)l * 4096 * 256;
    const float* wil = wi + (size_t)l * 4096 * 256;
    #pragma unroll
    for (int r = 0; r < 4; r++) {
        int row = tio * 32 + ty + 8 * r, col = tm * 32 + tx;
        size_t idx = (size_t)row * 256 + col;
        tile[ty + 8 * r][tx] = pk(wrl[idx], wil[idx]);
    }
    __syncthreads();
    #pragma unroll
    for (int r = 0; r < 4; r++) {
        int mm = tm * 32 + ty + 8 * r, io = tio * 32 + tx;
        g_W2[(((size_t)l * 256) + mm) * 4096 + io] = tile[tx][ty + 8 * r];
    }
}

// -------------------- gelu (exact erf) --------------------------------------
__device__ __forceinline__ float gelu_exact(float z) {
    return 0.5f * z * (1.0f + erff(z * 0.70710678118654752f));
}

// -------------------- shared epilogue: forward w-DFT from smem --------------
__device__ __forceinline__ void epilogue_fwd_w(const float* nxt_s, char* rb,
                                               int b, int h, int t) {
    ull* frp = (ull*)rb;
    ull* fip = (ull*)(rb + 16640);
    for (int i = t; i < 2048; i += 256) {
        int ky = i >> 7, j = i & 127;
        frp[ky * 130 + j] = g_FwR[i];
        fip[ky * 130 + j] = g_FwI[i];
    }
    __syncthreads();
    ull* Tg = g_T + ((size_t)b * C0) * 4096 + (size_t)h * MX;
    #pragma unroll
    for (int pass = 0; pass < 4; pass++) {
        int o = (t >> 4) + 16 * pass, ky = t & 15;
        const ull* fr = frp + ky * 130;
        const ull* fi = fip + ky * 130;
        const float* vs = nxt_s + o * 260;
        ull ar = 0ull, ai = 0ull;
        for (int iw = 0; iw < 64; iw++) {
            ulonglong2 vv = *(const ulonglong2*)(vs + iw * 4);
            ulonglong2 fR = *(const ulonglong2*)(fr + iw * 2);
            ulonglong2 fI = *(const ulonglong2*)(fi + iw * 2);
            ar = f2fma(vv.x, fR.x, ar); ar = f2fma(vv.y, fR.y, ar);
            ai = f2fma(vv.x, fI.x, ai); ai = f2fma(vv.y, fI.y, ai);
        }
        float r0, r1, i0, i1; upk(ar, r0, r1); upk(ai, i0, i1);
        Tg[(size_t)o * 4096 + ky] = pk(r0 + r1, i0 + i1);
    }
}

// -------------------- lift: 2->64 + fwd w-DFT -------------------------------
__global__ __launch_bounds__(256, 2)
void k_lift(const float* __restrict__ x, const float* __restrict__ in_w,
            const float* __restrict__ in_b) {
    extern __shared__ __align__(16) char smraw[];
    float* nxt_s = (float*)smraw;
    char* rb = smraw + 66560;
    __shared__ float siw[128], sib[64];
    int h = blockIdx.x, b = blockIdx.y, t = threadIdx.x;
    if (t < 128) siw[t] = in_w[t];
    if (t < 64) sib[t] = in_b[t];
    float x0 = x[(((size_t)b * 2 + 0) * Hh + h) * Ww + t];
    float x1 = x[(((size_t)b * 2 + 1) * Hh + h) * Ww + t];
    __syncthreads();
    size_t base = ((size_t)b * C0) * HW + (size_t)h * Ww + t;
    for (int o = 0; o < C0; o++) {
        float v = fmaf(siw[2 * o], x0, fmaf(siw[2 * o + 1], x1, sib[o]));
        nxt_s[o * 260 + t] = v;
        g_ha[base + (size_t)o * HW] = v;
    }
    __syncthreads();
    epilogue_fwd_w(nxt_s, rb, b, h, t);
}

// -------------------- forward h-DFT: T -> Xf --------------------------------
__global__ __launch_bounds__(256, 2) void k_fwd_h() {
    extern __shared__ __align__(16) char smraw[];
    ull* Ts = (ull*)smraw;                 // 4096 ull = 32KB
    ull* fa = Ts + 4096;                   // 32KB
    ull* fb = fa + 4096;                   // 32KB
    int bc = blockIdx.x, t = threadIdx.x;
    const ull* Tg = g_T + (size_t)bc * 4096;
    for (int i = t; i < 4096; i += 256) { Ts[i] = Tg[i]; fa[i] = g_Fh2a[i]; fb[i] = g_Fh2b[i]; }
    __syncthreads();
    int kx = t >> 4, ky = t & 15;
    const ull* fak = fa + kx * 256;
    const ull* fbk = fb + kx * 256;
    ull acc = 0ull;
    for (int h = 0; h < Hh; h++) {
        float tr, ti; upk(Ts[h * MX + ky], tr, ti);
        acc = f2fma(pk(tr, tr), fak[h], acc);
        acc = f2fma(pk(ti, ti), fbk[h], acc);
    }
    g_Xf[(size_t)bc * 256 + t] = acc;
}

// -------------------- per-mode complex channel GEMM -------------------------
__global__ __launch_bounds__(512, 2) void k_modegemm(int l) {
    __shared__ __align__(16) ull ws[4096];
    __shared__ ull xA[512], xB[512];
    int m = blockIdx.x, t = threadIdx.x;
    const ull* W = g_W2 + (((size_t)l * 256) + m) * 4096;
    for (int i = t; i < 4096; i += 512) ws[i] = W[i];
    {
        int b = t >> 6, i = t & 63;
        float xr, xi; upk(g_Xf[((size_t)b * C0 + i) * 256 + m], xr, xi);
        xA[t] = pk(xr, xr);
        xB[t] = pk(-xi, xi);
    }
    __syncthreads();
    int b = t >> 6, o = t & 63;
    ull acc = 0ull;
    const ull* xa = xA + b * 64;
    const ull* xb = xB + b * 64;
    #pragma unroll 4
    for (int i = 0; i < C0; i++) {
        ull w2 = ws[i * 64 + o];
        float wr, wi; upk(w2, wr, wi);
        acc = f2fma(xa[i], w2, acc);
        acc = f2fma(xb[i], pk(wi, wr), acc);
    }
    g_G[(size_t)m * 512 + t] = acc;
}

// -------------------- inverse kx stage: G -> Q ------------------------------
__global__ __launch_bounds__(256, 2) void k_inv_h() {
    extern __shared__ __align__(16) char smraw[];
    ull* Gs = (ull*)smraw;      // 256 ull
    ull* ea = Gs + 256;         // 4096 ull
    ull* eb = ea + 4096;        // 4096 ull
    int bo = blockIdx.x, t = threadIdx.x;
    for (int i = t; i < 256; i += 256) Gs[i] = g_G[(size_t)i * 512 + bo];
    for (int i = t; i < 4096; i += 256) { ea[i] = g_Eh2a[i]; eb[i] = g_Eh2b[i]; }
    __syncthreads();
    int hg = t >> 4, ky = t & 15;
    ull acc[16];
    #pragma unroll
    for (int i = 0; i < 16; i++) acc[i] = 0ull;
    #pragma unroll
    for (int kx = 0; kx < MX; kx++) {
        float gr, gi; upk(Gs[kx * MX + ky], gr, gi);
        ull gr2 = pk(gr, gr), gi2 = pk(gi, gi);
        #pragma unroll
        for (int hp = 0; hp < 16; hp++) {
            int h = hp * 16 + hg;
            acc[hp] = f2fma(gr2, ea[h * MX + kx], acc[hp]);
            acc[hp] = f2fma(gi2, eb[h * MX + kx], acc[hp]);
        }
    }
    ull* Qg = g_Q + (size_t)bo * 4096;
    #pragma unroll
    for (int hp = 0; hp < 16; hp++)
        Qg[(size_t)(hp * 16 + hg) * MX + ky] = acc[hp];
}

// -------------------- fused layer ------------------------------------------
template <bool WRITE_T>
__global__ __launch_bounds__(256, 2)
void k_layer(const float* __restrict__ cur, float* __restrict__ nxt,
             const float* __restrict__ pw_w, const float* __restrict__ pw_b) {
    extern __shared__ __align__(16) char smraw[];
    float* nxt_s = (float*)smraw;            // 64*260 floats
    char* rb = smraw + 66560;
    int h = blockIdx.x, b = blockIdx.y, t = threadIdx.x;

    float* pw_s = (float*)rb;                // 4096 floats
    ull* q_s = (ull*)(rb + 16384);           // 1024 ull
    for (int i = t; i < 4096; i += 256) pw_s[i] = pw_w[i];
    {
        const ull* Qg = g_Q + ((size_t)b * C0) * 4096 + (size_t)h * MX;
        for (int i = t; i < 1024; i += 256) {
            int o = i >> 4, ky = i & 15;
            q_s[i] = Qg[(size_t)o * 4096 + ky];
        }
    }
    ull ew[16];
    #pragma unroll
    for (int ky = 0; ky < MX; ky++) ew[ky] = g_Ew2n[ky * 256 + t];

    ull xr2[32];
    size_t base = ((size_t)b * C0) * HW + (size_t)h * Ww + t;
    #pragma unroll
    for (int j = 0; j < 32; j++) {
        float a = cur[base + (size_t)(2 * j) * HW];
        float c = cur[base + (size_t)(2 * j + 1) * HW];
        xr2[j] = pk(a, c);
    }
    __syncthreads();

    for (int o = 0; o < C0; o++) {
        ull acc = pk(__ldg(pw_b + o), 0.0f);
        const ulonglong2* wv = (const ulonglong2*)(pw_s + o * 64);
        #pragma unroll
        for (int j = 0; j < 16; j++) {
            ulonglong2 w2 = wv[j];
            acc = f2fma(w2.x, xr2[2 * j], acc);
            acc = f2fma(w2.y, xr2[2 * j + 1], acc);
        }
        const ulonglong2* q2 = (const ulonglong2*)(q_s + o * 16);
        #pragma unroll
        for (int k = 0; k < 8; k++) {
            ulonglong2 qq = q2[k];
            acc = f2fma(qq.x, ew[2 * k], acc);
            acc = f2fma(qq.y, ew[2 * k + 1], acc);
        }
        float lo, hi; upk(acc, lo, hi);
        float v = gelu_exact(lo + hi);
        nxt_s[o * 260 + t] = v;
        nxt[base + (size_t)o * HW] = v;
    }

    if (WRITE_T) {
        __syncthreads();
        epilogue_fwd_w(nxt_s, rb, b, h, t);
    }
}

// -------------------- head --------------------------------------------------
__global__ __launch_bounds__(256, 2)
void k_head(const float* __restrict__ cur, float* __restrict__ out,
            const float* __restrict__ o1w, const float* __restrict__ o1b,
            const float* __restrict__ o2w, const float* __restrict__ o2b) {
    __shared__ __align__(16) float w1[2048];
    __shared__ float w2[32], b1[32];
    int h = blockIdx.x, b = blockIdx.y, t = threadIdx.x;
    for (int i = t; i < 2048; i += 256) w1[i] = o1w[i];
    if (t < 32) { w2[t] = o2w[t]; b1[t] = o1b[t]; }

    ull xr2[32];
    size_t base = ((size_t)b * C0) * HW + (size_t)h * Ww + t;
    #pragma unroll
    for (int j = 0; j < 32; j++) {
        float a = cur[base + (size_t)(2 * j) * HW];
        float c = cur[base + (size_t)(2 * j + 1) * HW];
        xr2[j] = pk(a, c);
    }
    __syncthreads();

    float acc = __ldg(o2b);
    for (int o = 0; o < 32; o++) {
        ull s = pk(b1[o], 0.0f);
        const ulonglong2* wv = (const ulonglong2*)(w1 + o * 64);
        #pragma unroll
        for (int j = 0; j < 16; j++) {
            ulonglong2 p = wv[j];
            s = f2fma(p.x, xr2[2 * j], s);
            s = f2fma(p.y, xr2[2 * j + 1], s);
        }
        float lo, hi; upk(s, lo, hi);
        acc = fmaf(w2[o], gelu_exact(lo + hi), acc);
    }
    out[((size_t)b * Hh + h) * Ww + t] = acc;
}

// ---------------------------------------------------------------------------
extern "C" void kernel_launch(void* const* d_in, const int* in_sizes, int n_in,
                              void* d_out, int out_size) {
    const float* x       = (const float*)d_in[0];
    const float* in_w    = (const float*)d_in[1];
    const float* in_b    = (const float*)d_in[2];
    const float* spec_wr = (const float*)d_in[3];
    const float* spec_wi = (const float*)d_in[4];
    const float* pw_w    = (const float*)d_in[5];
    const float* pw_b    = (const float*)d_in[6];
    const float* o1w     = (const float*)d_in[7];
    const float* o1b     = (const float*)d_in[8];
    const float* o2w     = (const float*)d_in[9];
    const float* o2b     = (const float*)d_in[10];
    float* out = (float*)d_out;

    const int SMEM_L = 66560 + 33280;        // 99840
    const int SMEM_FH = 3 * 4096 * 8;        // 98304
    const int SMEM_IH = (256 + 2 * 4096) * 8;// 67584
    static int attr_done = 0;
    if (!attr_done) {
        cudaFuncSetAttribute(k_lift, cudaFuncAttributeMaxDynamicSharedMemorySize, SMEM_L);
        cudaFuncSetAttribute(k_layer<true>,  cudaFuncAttributeMaxDynamicSharedMemorySize, SMEM_L);
        cudaFuncSetAttribute(k_layer<false>, cudaFuncAttributeMaxDynamicSharedMemorySize, SMEM_L);
        cudaFuncSetAttribute(k_fwd_h, cudaFuncAttributeMaxDynamicSharedMemorySize, SMEM_FH);
        cudaFuncSetAttribute(k_inv_h, cudaFuncAttributeMaxDynamicSharedMemorySize, SMEM_IH);
        attr_done = 1;
    }

    float *ha, *hb;
    cudaGetSymbolAddress((void**)&ha, g_ha);
    cudaGetSymbolAddress((void**)&hb, g_hb);

    k_tables<<<16, 256>>>();
    k_tables2<<<8, 256>>>();
    k_twt<<<dim3(128, 8, NLAYERS), dim3(32, 8)>>>(spec_wr, spec_wi);

    dim3 grid(Hh, Bb);
    k_lift<<<grid, 256, SMEM_L>>>(x, in_w, in_b);

    const float* cur = ha;
    float* nxt = hb;
    for (int l = 0; l < NLAYERS; l++) {
        k_fwd_h<<<Bb * C0, 256, SMEM_FH>>>();
        k_modegemm<<<256, 512>>>(l);
        k_inv_h<<<Bb * C0, 256, SMEM_IH>>>();
        if (l < NLAYERS - 1)
            k_layer<true><<<grid, 256, SMEM_L>>>(cur, nxt, pw_w + l * 4096, pw_b + l * 64);
        else
            k_layer<false><<<grid, 256, SMEM_L>>>(cur, nxt, pw_w + l * 4096, pw_b + l * 64);
        const float* tmp = cur; cur = nxt; nxt = (float*)tmp;
    }

    k_head<<<grid, 256>>>(cur, out, o1w, o1b, o2w, o2b);
}